// round 5
// baseline (speedup 1.0000x reference)
#include <cuda_runtime.h>
#include <math.h>

#define BB    128
#define NN    22
#define FF    448
#define HD    64
#define NPAIR 484
#define NUP   231
#define NUPD  253
#define PSTR  65
#define XSS   452
#define XQF   1032

struct __align__(16) Smem {
    float xq[12 * XQF];          // packed pairs: [p][kk*2+parity]; kk<64 emb, >=64 x
    float xs[NN * XSS];          // row-major x
    float proj[4][NN * PSTR];    // u, v, p, q
    float gred[4 * 4 * 384];     // cross-warp k-split partials
    float sw2s[HD * 36];
    float corrs[NPAIR], gcs[NPAIR], adjs[NPAIR];
    float cw2s[HD], lngs[HD], lnbs[HD], sb2s[32], sw3s[32];
    float mu[NN], istd[NN];
    int   pl[NUP], plg[NUPD];
};

__device__ __forceinline__ void fma2b(float2& d, float x0, float x1, float w) {
    float2 a = make_float2(x0, x1);
    float2 b = make_float2(w, w);
    asm("fma.rn.f32x2 %0, %1, %2, %0;"
        : "+l"(*reinterpret_cast<unsigned long long*>(&d))
        : "l"(*reinterpret_cast<const unsigned long long*>(&a)),
          "l"(*reinterpret_cast<const unsigned long long*>(&b)));
}

__device__ __forceinline__ void fma2(float2& d, const float2 a, const float2 b) {
    asm("fma.rn.f32x2 %0, %1, %2, %0;"
        : "+l"(*reinterpret_cast<unsigned long long*>(&d))
        : "l"(*reinterpret_cast<const unsigned long long*>(&a)),
          "l"(*reinterpret_cast<const unsigned long long*>(&b)));
}

__device__ __forceinline__ float warpSum(float v) {
    #pragma unroll
    for (int o = 16; o; o >>= 1) v += __shfl_xor_sync(0xffffffffu, v, o);
    return v;
}

#define PSTEP(A, XV)                                              \
    fma2b(A[0], XV.x, XV.y, w0.x); fma2b(A[0], XV.z, XV.w, w1.x); \
    fma2b(A[1], XV.x, XV.y, w0.y); fma2b(A[1], XV.z, XV.w, w1.y); \
    fma2b(A[2], XV.x, XV.y, w0.z); fma2b(A[2], XV.z, XV.w, w1.z); \
    fma2b(A[3], XV.x, XV.y, w0.w); fma2b(A[3], XV.z, XV.w, w1.w);

__global__ __launch_bounds__(1024, 1)
void fused_kernel(const float* __restrict__ x,
                  const float* __restrict__ cw1, const float* __restrict__ cb1,
                  const float* __restrict__ cw2, const float* __restrict__ cb2,
                  const float* __restrict__ emb,
                  const float* __restrict__ sw1, const float* __restrict__ sb1,
                  const float* __restrict__ lng, const float* __restrict__ lnb,
                  const float* __restrict__ sw2, const float* __restrict__ sb2,
                  const float* __restrict__ sw3, const float* __restrict__ sb3,
                  const float* __restrict__ thr, const float* __restrict__ alpha_p,
                  float* __restrict__ out) {
    extern __shared__ __align__(16) char smem_raw[];
    Smem* s = reinterpret_cast<Smem*>(smem_raw);

    const int b    = blockIdx.x;
    const int tid  = threadIdx.x;
    const int warp = tid >> 5;
    const int lane = tid & 31;

    // ---------------- Phase 1: loads ----------------
    {
        const float* xb = x + (size_t)b * NN * FF;
        for (int idx = tid; idx < NN * FF; idx += 1024) {
            int i = idx / FF, k = idx - i * FF;
            float v = xb[idx];
            s->xs[i * XSS + k] = v;
            s->xq[(i >> 1) * XQF + (64 + k) * 2 + (i & 1)] = v;
        }
        for (int idx = tid; idx < NN * HD; idx += 1024) {
            int i = idx >> 6, k = idx & 63;
            s->xq[(i >> 1) * XQF + k * 2 + (i & 1)] = emb[idx];
        }
        for (int idx = tid; idx < XQF; idx += 1024) s->xq[11 * XQF + idx] = 0.f;
        for (int idx = tid; idx < HD * 32; idx += 1024) {
            int c = idx >> 5, o = idx & 31;
            s->sw2s[c * 36 + o] = sw2[idx];
        }
        if (tid < NPAIR) s->adjs[tid] = 0.f;
        if (tid < HD) { s->cw2s[tid] = cw2[tid]; s->lngs[tid] = lng[tid]; s->lnbs[tid] = lnb[tid]; }
        if (tid >= HD && tid < HD + 32) { s->sb2s[tid - HD] = sb2[tid - HD]; s->sw3s[tid - HD] = sw3[tid - HD]; }
        if (tid < NPAIR) {
            int i = tid / NN, j = tid - i * NN;
            if (i < j)  s->pl [i * (2 * NN - 1 - i) / 2 + (j - i - 1)] = (i << 5) | j;
            if (i <= j) s->plg[i * (2 * NN + 1 - i) / 2 + (j - i)]     = (i << 5) | j;
        }
    }
    __syncthreads();

    // ---------------- Phase 2: GEMM (k-split 4) ----------------
    const int m   = tid >> 8;
    const int ksw = (tid >> 7) & 1;
    const int pg  = (tid >> 5) & 3;
    const int ksl = (tid >> 4) & 1;
    const int ci  = tid & 15;
    const int c0  = ci * 4;
    const int ks  = ksw * 2 + ksl;
    const int p0  = pg * 3;

    float2 acc[3][4];
    #pragma unroll
    for (int pp = 0; pp < 3; pp++)
        #pragma unroll
        for (int cc = 0; cc < 4; cc++) acc[pp][cc] = make_float2(0.f, 0.f);

    {
        int rowB;
        if      (m == 0) rowB = ks * 112;
        else if (m == 1) rowB = 448 + ks * 112;
        else if (m == 2) rowB = 128 + ks * 112;
        else             rowB = 576 + ks * 112;
        const float* wB = ((m < 2) ? cw1 : sw1) + rowB * HD + c0;

        const float4* xr0 = reinterpret_cast<const float4*>(s->xq + (p0 + 0) * XQF + 128 + ks * 224);
        const float4* xr1 = reinterpret_cast<const float4*>(s->xq + (p0 + 1) * XQF + 128 + ks * 224);
        const float4* xr2 = reinterpret_cast<const float4*>(s->xq + (p0 + 2) * XQF + 128 + ks * 224);

        #pragma unroll 4
        for (int it = 0; it < 56; it++) {
            float4 w0 = *reinterpret_cast<const float4*>(wB);
            float4 w1 = *reinterpret_cast<const float4*>(wB + HD);
            wB += 2 * HD;
            float4 xa  = xr0[it];
            float4 xb4 = xr1[it];
            float4 xc  = xr2[it];
            PSTEP(acc[0], xa);
            PSTEP(acc[1], xb4);
            PSTEP(acc[2], xc);
        }

        if (m >= 2) {  // emb prefix (64 virtual k rows, 16 per ks)
            const float* wA = sw1 + ((m == 3 ? 64 : 0) + ks * 16) * HD + c0;
            const float4* ar0 = reinterpret_cast<const float4*>(s->xq + (p0 + 0) * XQF + ks * 32);
            const float4* ar1 = reinterpret_cast<const float4*>(s->xq + (p0 + 1) * XQF + ks * 32);
            const float4* ar2 = reinterpret_cast<const float4*>(s->xq + (p0 + 2) * XQF + ks * 32);
            #pragma unroll 4
            for (int it = 0; it < 8; it++) {
                float4 w0 = *reinterpret_cast<const float4*>(wA);
                float4 w1 = *reinterpret_cast<const float4*>(wA + HD);
                wA += 2 * HD;
                float4 xa  = ar0[it];
                float4 xb4 = ar1[it];
                float4 xc  = ar2[it];
                PSTEP(acc[0], xa);
                PSTEP(acc[1], xb4);
                PSTEP(acc[2], xc);
            }
        }

        // in-warp reduce (ksl halves, lane xor 16)
        #pragma unroll
        for (int pp = 0; pp < 3; pp++)
            #pragma unroll
            for (int cc = 0; cc < 4; cc++) {
                unsigned long long v = *reinterpret_cast<unsigned long long*>(&acc[pp][cc]);
                unsigned long long o = __shfl_xor_sync(0xffffffffu, v, 16);
                float2 ov = *reinterpret_cast<float2*>(&o);
                acc[pp][cc].x += ov.x;
                acc[pp][cc].y += ov.y;
            }

        // cross-warp partials: ksw=1 warps stash to smem
        if (ksw == 1 && ksl == 0) {
            float* gr = s->gred + (m * 4 + pg) * 384 + c0;
            #pragma unroll
            for (int pp = 0; pp < 3; pp++) {
                *reinterpret_cast<float4*>(gr + pp * 128) =
                    make_float4(acc[pp][0].x, acc[pp][1].x, acc[pp][2].x, acc[pp][3].x);
                *reinterpret_cast<float4*>(gr + pp * 128 + 64) =
                    make_float4(acc[pp][0].y, acc[pp][1].y, acc[pp][2].y, acc[pp][3].y);
            }
        }
    }
    __syncthreads();

    // ---------------- Phase 3: combine (ksw=0 warps) || stats (ksw=1 warps) ----------------
    if (ksw == 0) {
        if (ksl == 0) {
            const float* gr = s->gred + (m * 4 + pg) * 384 + c0;
            float4 bb = make_float4(0.f, 0.f, 0.f, 0.f);
            if (m == 0) bb = *reinterpret_cast<const float4*>(cb1 + c0);
            if (m == 2) bb = *reinterpret_cast<const float4*>(sb1 + c0);
            float bcol[4] = {bb.x, bb.y, bb.z, bb.w};
            const int npp = (pg == 3) ? 2 : 3;
            float* pm = s->proj[m];
            #pragma unroll
            for (int pp = 0; pp < 3; pp++) {
                if (pp < npp) {
                    float4 ox = *reinterpret_cast<const float4*>(gr + pp * 128);
                    float4 oy = *reinterpret_cast<const float4*>(gr + pp * 128 + 64);
                    float oxa[4] = {ox.x, ox.y, ox.z, ox.w};
                    float oya[4] = {oy.x, oy.y, oy.z, oy.w};
                    int r0 = (p0 + pp) * 2;
                    #pragma unroll
                    for (int cc = 0; cc < 4; cc++) {
                        pm[r0 * PSTR + c0 + cc]       = acc[pp][cc].x + oxa[cc] + bcol[cc];
                        pm[(r0 + 1) * PSTR + c0 + cc] = acc[pp][cc].y + oya[cc] + bcol[cc];
                    }
                }
            }
        }
    } else {
        const int sIdx = (warp >> 3) * 4 + (warp & 3);  // 0..15
        for (int i = sIdx; i < NN; i += 16) {
            float smv = 0.f, sq = 0.f;
            const float* r = s->xs + i * XSS;
            for (int k = lane * 4; k < FF; k += 128) {
                float4 v = *reinterpret_cast<const float4*>(r + k);
                smv += v.x + v.y + v.z + v.w;
                sq  += v.x * v.x + v.y * v.y + v.z * v.z + v.w * v.w;
            }
            smv = warpSum(smv); sq = warpSum(sq);
            if (lane == 0) {
                float mm  = smv / FF;
                float var = (sq - FF * mm * mm) / (FF - 1);
                var = fmaxf(var, 0.f);
                s->mu[i]   = mm;
                s->istd[i] = 1.0f / (sqrtf(var) + 1e-8f);
            }
        }
    }
    __syncthreads();

    // ---------------- Phase 4: gram/corr (warp per pair) ----------------
    for (int pi = warp; pi < NUPD; pi += 32) {
        int code = s->plg[pi];
        int i = code >> 5, j = code & 31;
        const float* ri = s->xs + i * XSS;
        const float* rj = s->xs + j * XSS;
        float dot = 0.f;
        for (int k = lane * 4; k < FF; k += 128) {
            float4 a = *reinterpret_cast<const float4*>(ri + k);
            float4 c = *reinterpret_cast<const float4*>(rj + k);
            dot += a.x * c.x + a.y * c.y + a.z * c.z + a.w * c.w;
        }
        dot = warpSum(dot);
        if (lane == 0) {
            float cv = fabsf((dot - (float)FF * s->mu[i] * s->mu[j]) * s->istd[i] * s->istd[j]) * (1.0f / FF);
            s->corrs[i * NN + j] = cv;
            s->corrs[j * NN + i] = cv;
        }
    }
    __syncthreads();

    // ---------------- Phase 5: semantic MLP (tid<512, 2 threads/pair) || corr MLP (tid>=512) ----------------
    if (tid < 512) {
        const float tthr = 1.0f / (1.0f + __expf(-thr[0]));
        int pr = tid >> 1;
        if (pr > NUP - 1) pr = NUP - 1;
        const int half = tid & 1;
        int code = s->pl[pr];
        int i = code >> 5, j = code & 31;
        const float* pi = s->proj[2] + i * PSTR + half * 32;
        const float* qj = s->proj[3] + j * PSTR + half * 32;
        float smv = 0.f, sq = 0.f;
        #pragma unroll 4
        for (int c = 0; c < 32; c++) {
            float sv = pi[c] + qj[c];
            smv += sv; sq += sv * sv;
        }
        smv += __shfl_xor_sync(0xffffffffu, smv, 1);
        sq  += __shfl_xor_sync(0xffffffffu, sq, 1);
        float muv  = smv * (1.0f / HD);
        float var  = sq * (1.0f / HD) - muv * muv;
        float rstd = rsqrtf(var + 1e-5f);

        float2 h2p[16];
        #pragma unroll
        for (int o = 0; o < 16; o++)
            h2p[o] = half ? make_float2(0.f, 0.f)
                          : make_float2(s->sb2s[2 * o], s->sb2s[2 * o + 1]);
        const int cb = half * 32;
        #pragma unroll 2
        for (int c = 0; c < 32; c++) {
            float sv = pi[c] + qj[c];
            float h1 = fmaxf((sv - muv) * rstd * s->lngs[cb + c] + s->lnbs[cb + c], 0.f);
            float2 h1d = make_float2(h1, h1);
            const float4* wr = reinterpret_cast<const float4*>(s->sw2s + (cb + c) * 36);
            #pragma unroll
            for (int o4 = 0; o4 < 8; o4++) {
                float4 w = wr[o4];
                fma2(h2p[2 * o4],     h1d, make_float2(w.x, w.y));
                fma2(h2p[2 * o4 + 1], h1d, make_float2(w.z, w.w));
            }
        }
        // combine halves
        #pragma unroll
        for (int o = 0; o < 16; o++) {
            h2p[o].x += __shfl_xor_sync(0xffffffffu, h2p[o].x, 1);
            h2p[o].y += __shfl_xor_sync(0xffffffffu, h2p[o].y, 1);
        }
        float z = sb3[0];
        #pragma unroll
        for (int o = 0; o < 16; o++) {
            z += fmaxf(h2p[o].x, 0.f) * s->sw3s[2 * o];
            z += fmaxf(h2p[o].y, 0.f) * s->sw3s[2 * o + 1];
        }
        float ws  = 1.0f / (1.0f + __expf(-z));
        float val = (ws > tthr) ? ws : 0.f;
        if (tid < 2 * NUP) {
            if (half == 0) s->adjs[i * NN + j] = val;
            else           s->adjs[j * NN + i] = val;
        }
    } else {
        const float cb2v = cb2[0];
        const int pidx = tid - 512;
        if (pidx < NPAIR) {
            int i = pidx / NN, j = pidx - i * NN;
            const float* ui = s->proj[0] + i * PSTR;
            const float* vj = s->proj[1] + j * PSTR;
            float z = cb2v;
            #pragma unroll 4
            for (int c = 0; c < HD; c++)
                z += fmaxf(ui[c] + vj[c], 0.f) * s->cw2s[c];
            float wc = 1.0f / (1.0f + __expf(-z));
            s->gcs[pidx] = s->corrs[pidx] * wc;
        }
    }
    __syncthreads();

    // ---------------- Phase 6: fuse + store ----------------
    if (tid < NPAIR) {
        const float alpha = 1.0f / (1.0f + __expf(-alpha_p[0]));
        int i = tid / NN, j = tid - i * NN;
        float eye = (i == j) ? 1.0f : 0.0f;
        out[(size_t)b * NPAIR + tid] = alpha * s->gcs[tid] + (1.0f - alpha) * s->adjs[tid] + eye;
    }
}

extern "C" void kernel_launch(void* const* d_in, const int* in_sizes, int n_in,
                              void* d_out, int out_size) {
    const float* x       = (const float*)d_in[0];
    const float* cw1     = (const float*)d_in[1];
    const float* cb1     = (const float*)d_in[2];
    const float* cw2     = (const float*)d_in[3];
    const float* cb2     = (const float*)d_in[4];
    const float* emb     = (const float*)d_in[5];
    const float* sw1     = (const float*)d_in[6];
    const float* sb1     = (const float*)d_in[7];
    const float* ln_g    = (const float*)d_in[8];
    const float* ln_b    = (const float*)d_in[9];
    const float* sw2     = (const float*)d_in[10];
    const float* sb2     = (const float*)d_in[11];
    const float* sw3     = (const float*)d_in[12];
    const float* sb3     = (const float*)d_in[13];
    const float* thr     = (const float*)d_in[14];
    const float* alpha_p = (const float*)d_in[15];
    float* out = (float*)d_out;

    static bool attr_set = false;
    if (!attr_set) {
        cudaFuncSetAttribute(fused_kernel, cudaFuncAttributeMaxDynamicSharedMemorySize,
                             (int)sizeof(Smem));
        attr_set = true;
    }
    fused_kernel<<<BB, 1024, sizeof(Smem)>>>(x, cw1, cb1, cw2, cb2, emb, sw1, sb1,
                                             ln_g, ln_b, sw2, sb2, sw3, sb3, thr, alpha_p, out);
}